// round 14
// baseline (speedup 1.0000x reference)
#include <cuda_runtime.h>
#include <math.h>

#define D 128
#define KNBR 5
#define NMAX 300000

// ---------------- scratch (static device memory; no allocations allowed) ----
__device__ float g_Q1[(size_t)NMAX * D];
__device__ float g_K1[(size_t)NMAX * D];
__device__ float g_V1[(size_t)NMAX * D];
__device__ float g_K2[(size_t)NMAX * D];
__device__ float g_V2[(size_t)NMAX * D];
__device__ float g_Q2[(size_t)NMAX * D];
__device__ float g_ATT[(size_t)NMAX * D];
__device__ float g_XB[(size_t)NMAX * D];
__device__ float g_aw[(size_t)NMAX * 40];   // softmax weights [N][j=5][h=8]
__device__ float g_rs[NMAX];
__device__ int   g_validbyte;
__device__ float g_Wr[270336];              // tf32-pre-rounded weights

#define OFF_WQ1 0
#define OFF_WK1 16384
#define OFF_WV1 32768
#define OFF_WK2 49152
#define OFF_WV2 65536
#define OFF_WO1 81920
#define OFF_W1A 98304
#define OFF_W1B 131072
#define OFF_WQ2 163840
#define OFF_WO2 180224
#define OFF_W2A 196608
#define OFF_W2B 229376
#define OFF_W4  262144

// ---------------- detect whether nbr_valid is byte-bool or int32 ------------
__global__ void detect_valid_kernel(const unsigned char* __restrict__ p, int nelem) {
    if (threadIdx.x == 0) g_validbyte = 0;
    __syncthreads();
    int lim = nelem < 4096 ? nelem : 4096;
    int found = 0;
    for (int j = threadIdx.x; j < lim; j += blockDim.x)
        if ((j & 3) && p[j]) found = 1;
    if (found) g_validbyte = 1;
}

// ---------------- tf32 / mma / cp.async helpers ------------------------------
__device__ __forceinline__ unsigned f2tf32(float f) {
    unsigned u;
    asm("cvt.rna.tf32.f32 %0, %1;" : "=r"(u) : "f"(f));
    return u;
}
__device__ __forceinline__ float rnd_tf32(float f) { return __uint_as_float(f2tf32(f)); }

__device__ __forceinline__ void mma_tf32(float* c, const unsigned* a, const unsigned* b) {
    asm volatile(
        "mma.sync.aligned.m16n8k8.row.col.f32.tf32.tf32.f32 "
        "{%0,%1,%2,%3}, {%4,%5,%6,%7}, {%8,%9}, {%0,%1,%2,%3};"
        : "+f"(c[0]), "+f"(c[1]), "+f"(c[2]), "+f"(c[3])
        : "r"(a[0]), "r"(a[1]), "r"(a[2]), "r"(a[3]), "r"(b[0]), "r"(b[1]));
}

__device__ __forceinline__ void cp16(float* dst, const float* src, bool pred) {
    unsigned sa = (unsigned)__cvta_generic_to_shared(dst);
    int sz = pred ? 16 : 0;
    asm volatile("cp.async.cg.shared.global [%0], [%1], 16, %2;"
                 :: "r"(sa), "l"(src), "r"(sz) : "memory");
}
#define CP_COMMIT asm volatile("cp.async.commit_group;" ::: "memory")
__device__ __forceinline__ void cp_wait0() { asm volatile("cp.async.wait_group 0;" ::: "memory"); }

// ---------------- weight pre-rounding pass -----------------------------------
struct PrepList { const float* src[13]; int len[13]; int off[13]; };

__global__ void prep_weights(PrepList pl, float* __restrict__ dst) {
    int stride = gridDim.x * blockDim.x;
    int t = blockIdx.x * blockDim.x + threadIdx.x;
    #pragma unroll 1
    for (int e = 0; e < 13; e++) {
        const float* s = pl.src[e];
        float* d = dst + pl.off[e];
        for (int i = t; i < pl.len[e]; i += stride)
            d[i] = rnd_tf32(s[i]);
    }
}

// ============================================================================
//  Fragment compute: A chunk [64][20], B stage [16][136]; pre-rounded operands.
// ============================================================================
template <int NT>
__device__ __forceinline__ void compute_stageN(
    const float* __restrict__ Asm, const float* __restrict__ Bsm,
    int lane, int mrow, int ncol, float (&c)[2][NT][4])
{
    #pragma unroll
    for (int ks = 0; ks < 16; ks += 8) {
        int kq = ks + (lane & 3);
        unsigned a[2][4], b[NT][2];
        #pragma unroll
        for (int mt = 0; mt < 2; mt++) {
            int row = mrow + mt * 16 + (lane >> 2);
            a[mt][0] = __float_as_uint(Asm[row * 20 + kq]);
            a[mt][1] = __float_as_uint(Asm[(row + 8) * 20 + kq]);
            a[mt][2] = __float_as_uint(Asm[row * 20 + kq + 4]);
            a[mt][3] = __float_as_uint(Asm[(row + 8) * 20 + kq + 4]);
        }
        #pragma unroll
        for (int nt = 0; nt < NT; nt++) {
            int col = ncol + nt * 8 + (lane >> 2);
            b[nt][0] = __float_as_uint(Bsm[kq * 136 + col]);
            b[nt][1] = __float_as_uint(Bsm[(kq + 4) * 136 + col]);
        }
        #pragma unroll
        for (int mt = 0; mt < 2; mt++)
            #pragma unroll
            for (int nt = 0; nt < NT; nt++)
                mma_tf32(c[mt][nt], a[mt], b[nt]);
    }
}

// Stream B (K=128, 8 stages of 16) against a resident A region [8][64][20].
// ONE __syncthreads per stage: wait0 -> sync -> issue(it+1) -> compute(it).
// The single barrier guarantees stage-it data landed for all warps AND all
// warps finished stage it-1 (so buffer (it+1)&1 is safe to overwrite).
template <int NT>
__device__ __forceinline__ void gemm_stream(
    const float* __restrict__ Areg, const float* __restrict__ W,
    int pitch, int colOff, float* __restrict__ Bsm,
    int tid, int lane, int mrow, int ncol, float (&c)[2][NT][4])
{
    constexpr int PERROW = NT * 8;            // cp16 per B k-row
    constexpr int ITER   = (16 * PERROW) / 256;
    #pragma unroll
    for (int r = 0; r < ITER; r++) {
        int idx = tid + r * 256;
        int bk = idx / PERROW, bc = (idx % PERROW) * 4;
        cp16(&Bsm[bk * 136 + bc], W + (size_t)bk * pitch + colOff + bc, true);
    }
    CP_COMMIT;
    #pragma unroll
    for (int it = 0; it < 8; it++) {
        cp_wait0();
        __syncthreads();
        if (it < 7) {
            int st = (it + 1) & 1, k0 = (it + 1) * 16;
            #pragma unroll
            for (int r = 0; r < ITER; r++) {
                int idx = tid + r * 256;
                int bk = idx / PERROW, bc = (idx % PERROW) * 4;
                cp16(&Bsm[st * 2176 + bk * 136 + bc],
                     W + (size_t)(k0 + bk) * pitch + colOff + bc, true);
            }
            CP_COMMIT;
        }
        compute_stageN<NT>(Areg + it * 1280, Bsm + (it & 1) * 2176, lane, mrow, ncol, c);
    }
}

// bias + residual (global or smem A-layout) + LayerNorm; output (tf32-rounded)
// to smem A-layout and/or global. Overwrites c with pre-LN values.
__device__ __forceinline__ void ln_epi(
    float (&c)[2][4][4], const float* __restrict__ bias,
    const float* __restrict__ resg, const float* __restrict__ ressm,
    const float* __restrict__ gam, const float* __restrict__ bet,
    float2* __restrict__ red, float* __restrict__ outsm, float* __restrict__ outg,
    int row0, int M, int lane, int warp, int mrow, int ncol)
{
    int warpN = warp & 3;
    #pragma unroll
    for (int mt = 0; mt < 2; mt++)
        #pragma unroll
        for (int rh = 0; rh < 2; rh++) {
            int rl = mrow + mt * 16 + rh * 8 + (lane >> 2);
            bool ok = row0 + rl < M;
            float s = 0.f, sq = 0.f;
            #pragma unroll
            for (int nt = 0; nt < 4; nt++) {
                int col = ncol + nt * 8 + (lane & 3) * 2;
                float2 rr;
                if (ressm) rr = *(const float2*)&ressm[(col >> 4) * 1280 + rl * 20 + (col & 15)];
                else rr = ok ? *(const float2*)&resg[(size_t)(row0 + rl) * 128 + col]
                             : make_float2(0.f, 0.f);
                float2 bb = *(const float2*)&bias[col];
                float x0 = c[mt][nt][rh * 2 + 0] + rr.x + bb.x;
                float x1 = c[mt][nt][rh * 2 + 1] + rr.y + bb.y;
                c[mt][nt][rh * 2 + 0] = x0;
                c[mt][nt][rh * 2 + 1] = x1;
                s += x0 + x1;
                sq += x0 * x0 + x1 * x1;
            }
            s  += __shfl_xor_sync(0xffffffffu, s, 1);
            s  += __shfl_xor_sync(0xffffffffu, s, 2);
            sq += __shfl_xor_sync(0xffffffffu, sq, 1);
            sq += __shfl_xor_sync(0xffffffffu, sq, 2);
            if ((lane & 3) == 0) red[rl * 4 + warpN] = make_float2(s, sq);
        }
    __syncthreads();
    #pragma unroll
    for (int mt = 0; mt < 2; mt++)
        #pragma unroll
        for (int rh = 0; rh < 2; rh++) {
            int rl = mrow + mt * 16 + rh * 8 + (lane >> 2);
            float s = 0.f, sq = 0.f;
            #pragma unroll
            for (int wN = 0; wN < 4; wN++) { float2 e = red[rl * 4 + wN]; s += e.x; sq += e.y; }
            float mean = s * (1.f / 128.f);
            float var  = sq * (1.f / 128.f) - mean * mean;
            float rstd = rsqrtf(var + 1e-5f);
            bool ok = row0 + rl < M;
            #pragma unroll
            for (int nt = 0; nt < 4; nt++) {
                int col = ncol + nt * 8 + (lane & 3) * 2;
                float2 gg = *(const float2*)&gam[col];
                float2 ee = *(const float2*)&bet[col];
                float2 o;
                o.x = rnd_tf32((c[mt][nt][rh * 2 + 0] - mean) * rstd * gg.x + ee.x);
                o.y = rnd_tf32((c[mt][nt][rh * 2 + 1] - mean) * rstd * gg.y + ee.y);
                if (outsm) *(float2*)&outsm[(col >> 4) * 1280 + rl * 20 + (col & 15)] = o;
                if (outg && ok) *(float2*)&outg[(size_t)(row0 + rl) * 128 + col] = o;
            }
        }
    __syncthreads();
}

// relu(c + bias) -> smem A-layout (tf32-rounded); zeros c for reuse.
__device__ __forceinline__ void store_relu_sm(
    float (&c)[2][4][4], const float* __restrict__ bias, float* __restrict__ outsm,
    int lane, int mrow, int ncol)
{
    #pragma unroll
    for (int mt = 0; mt < 2; mt++)
        #pragma unroll
        for (int rh = 0; rh < 2; rh++) {
            int rl = mrow + mt * 16 + rh * 8 + (lane >> 2);
            #pragma unroll
            for (int nt = 0; nt < 4; nt++) {
                int col = ncol + nt * 8 + (lane & 3) * 2;
                float2 bb = *(const float2*)&bias[col];
                float2 o;
                o.x = rnd_tf32(fmaxf(c[mt][nt][rh * 2 + 0] + bb.x, 0.f));
                o.y = rnd_tf32(fmaxf(c[mt][nt][rh * 2 + 1] + bb.y, 0.f));
                *(float2*)&outsm[(col >> 4) * 1280 + rl * 20 + (col & 15)] = o;
                c[mt][nt][rh * 2 + 0] = 0.f;
                c[mt][nt][rh * 2 + 1] = 0.f;
            }
        }
}

// ============================================================================
//  Mega layer kernel: 64-row tile, 256 threads, 2 CTAs/SM.
// ============================================================================
template <int NP, int WRITE_XB, int POSTTANH>
__global__ void __launch_bounds__(256, 2) layer_kernel(
    const float* __restrict__ ATT, const float* __restrict__ wo, const float* __restrict__ bo,
    const float* __restrict__ res, const float* __restrict__ ga, const float* __restrict__ bea,
    const float* __restrict__ wa, const float* __restrict__ ba,
    const float* __restrict__ wb, const float* __restrict__ bb,
    const float* __restrict__ gb, const float* __restrict__ beb,
    const float* __restrict__ Wp, const float* __restrict__ bp,
    float* __restrict__ XB, float* __restrict__ Yp, int M)
{
    extern __shared__ float sm[];
    float*  R1  = sm;                        // XA, [8][64][20]
    float*  R2  = R1 + 8 * 64 * 20;          // ATT / H-half / XB tile
    float*  Bsm = R2 + 8 * 64 * 20;          // [2][16][136]
    float2* red = (float2*)(Bsm + 2 * 16 * 136);   // [64][4]

    int row0 = blockIdx.x * 64;
    int tid = threadIdx.x, lane = tid & 31, warp = tid >> 5;
    int mrow = (warp >> 2) * 32;
    int ncol = (warp & 3) * 32;

    // stage ATT tile -> R2 (ATT is pre-rounded tf32 by attn_apply)
    {
        int row = tid >> 2, seg = (tid & 3) * 4;
        bool ok = row0 + row < M;
        const float* src = ATT + (size_t)(row0 + row) * 128 + seg;
        #pragma unroll
        for (int kc = 0; kc < 8; kc++)
            cp16(&R2[kc * 1280 + row * 20 + seg], ok ? src + kc * 16 : ATT, ok);
        CP_COMMIT;
    }

    float cA[2][4][4] = {};
    float cB[2][4][4] = {};

    // P1: cA = ATT @ wo
    gemm_stream<4>(R2, wo, 128, 0, Bsm, tid, lane, mrow, ncol, cA);
    // P2: XA = LN(cA + bo + res) -> R1 (smem only)
    ln_epi(cA, bo, res, nullptr, ga, bea, red, R1, nullptr, row0, M, lane, warp, mrow, ncol);

    #pragma unroll
    for (int mt = 0; mt < 2; mt++)
        #pragma unroll
        for (int nt = 0; nt < 4; nt++)
            #pragma unroll
            for (int q = 0; q < 4; q++) cA[mt][nt][q] = 0.f;

    // FFN in two 128-col halves, H resident in R2
    #pragma unroll
    for (int h = 0; h < 2; h++) {
        gemm_stream<4>(R1, wa, 256, h * 128, Bsm, tid, lane, mrow, ncol, cA);
        store_relu_sm(cA, ba + h * 128, R2, lane, mrow, ncol);   // also zeros cA
        gemm_stream<4>(R2, wb + (size_t)h * 128 * 128, 128, 0, Bsm, tid, lane, mrow, ncol, cB);
    }

    // XB = LN(cB + bb + XA[smem]) -> R2 (for post) and optionally global
    ln_epi(cB, bb, nullptr, R1, gb, beb, red, R2, WRITE_XB ? XB : nullptr,
           row0, M, lane, warp, mrow, ncol);

    // post: Yp = act(XB @ Wp + bp)
    constexpr int NTP = NP / 32;
    int ncolp = (warp & 3) * (NTP * 8);
    float cP[2][NTP][4] = {};
    gemm_stream<NTP>(R2, Wp, NP, 0, Bsm, tid, lane, mrow, ncolp, cP);

    const bool hasb = (bp != nullptr);
    #pragma unroll
    for (int mt = 0; mt < 2; mt++)
        #pragma unroll
        for (int rh = 0; rh < 2; rh++) {
            int rl = mrow + mt * 16 + rh * 8 + (lane >> 2);
            if (row0 + rl >= M) continue;
            #pragma unroll
            for (int nt = 0; nt < NTP; nt++) {
                int col = ncolp + nt * 8 + (lane & 3) * 2;
                float bx = 0.f, by = 0.f;
                if (hasb) { float2 v = *(const float2*)&bp[col]; bx = v.x; by = v.y; }
                float x0 = cP[mt][nt][rh * 2 + 0] + bx;
                float x1 = cP[mt][nt][rh * 2 + 1] + by;
                if (POSTTANH) { x0 = tanhf(x0); x1 = tanhf(x1); }
                *(float2*)&Yp[(size_t)(row0 + rl) * NP + col] = make_float2(x0, x1);
            }
        }
}

// ---------------- proj5: fused 5-way projection, 64-row tile, 2 CTAs/SM ------
struct Proj5 { const float* W[5]; float* Y[5]; };

__global__ void __launch_bounds__(256, 2) proj5_kernel(
    const float* __restrict__ X, Proj5 p, float* __restrict__ rs, int M)
{
    extern __shared__ float sm[];
    float* Af = sm;                          // [8][64][20]
    float* Bs = sm + 8 * 64 * 20;            // [2][16][136]
    int row0 = blockIdx.x * 64;
    int tid = threadIdx.x, lane = tid & 31, warp = tid >> 5;
    int mrow = (warp >> 2) * 32, ncol = (warp & 3) * 32;

    // load full A tile (8 k-chunks), 4 threads per row
    {
        int row = tid >> 2, seg = (tid & 3) * 4;
        bool ok = (row0 + row) < M;
        const float* sa = X + (size_t)(row0 + row) * 128 + seg;
        #pragma unroll
        for (int kc = 0; kc < 8; kc++)
            cp16(&Af[kc * 1280 + row * 20 + seg], ok ? sa + kc * 16 : X, ok);
        CP_COMMIT;
    }
    int s_bk = tid >> 4;
    int s_bc = (tid & 15) * 8;
    {
        const float* sb = p.W[0] + (size_t)s_bk * 128 + s_bc;
        cp16(&Bs[s_bk * 136 + s_bc],     sb,     true);
        cp16(&Bs[s_bk * 136 + s_bc + 4], sb + 4, true);
        CP_COMMIT;
    }

    float c[2][4][4] = {};
    for (int it = 0; it < 40; it++) {
        int kc = it & 7;
        cp_wait0();
        __syncthreads();
        if (it + 1 < 40) {
            int st = (it + 1) & 1;
            const float* Wn = p.W[(it + 1) >> 3];
            int k0 = ((it + 1) & 7) * 16;
            const float* sb = Wn + (size_t)(k0 + s_bk) * 128 + s_bc;
            cp16(&Bs[st * 2176 + s_bk * 136 + s_bc],     sb,     true);
            cp16(&Bs[st * 2176 + s_bk * 136 + s_bc + 4], sb + 4, true);
            CP_COMMIT;
        }
        if (it == 0) {
            // rowsum for the mask, from the resident A tile (4 threads/row)
            int row = tid >> 2, part = tid & 3;
            float s = 0.f;
            #pragma unroll
            for (int q = 0; q < 2; q++) {
                int kcc = part * 2 + q;
                #pragma unroll
                for (int kl = 0; kl < 16; kl++) s += Af[kcc * 1280 + row * 20 + kl];
            }
            s += __shfl_xor_sync(0xffffffffu, s, 1);
            s += __shfl_xor_sync(0xffffffffu, s, 2);
            if ((lane & 3) == 0 && row0 + row < M) rs[row0 + row] = s;
        }
        compute_stageN<4>(Af + kc * 1280, Bs + (it & 1) * 2176, lane, mrow, ncol, c);
        if (kc == 7) {
            float* Y = p.Y[it >> 3];
            #pragma unroll
            for (int mt = 0; mt < 2; mt++)
                #pragma unroll
                for (int nt = 0; nt < 4; nt++) {
                    int col = ncol + nt * 8 + (lane & 3) * 2;
                    #pragma unroll
                    for (int rh = 0; rh < 2; rh++) {
                        int row = row0 + mrow + mt * 16 + rh * 8 + (lane >> 2);
                        if (row < M)
                            *(float2*)&Y[(size_t)row * 128 + col] =
                                make_float2(c[mt][nt][rh * 2 + 0], c[mt][nt][rh * 2 + 1]);
                        c[mt][nt][rh * 2 + 0] = 0.f;
                        c[mt][nt][rh * 2 + 1] = 0.f;
                    }
                }
        }
    }
}

// ---------------- two-pass attention -----------------------------------------
// pass 1: gather K only; per-head softmax weights -> aw[i][j][h]  (40 floats)
__global__ void attn_dots(const float* __restrict__ Q, const float* __restrict__ Kp,
                          const int* __restrict__ nbr, const void* __restrict__ validp,
                          const float* __restrict__ rs, float* __restrict__ aw, int N) {
    int warp = (blockIdx.x * blockDim.x + threadIdx.x) >> 5;
    int lane = threadIdx.x & 31;
    if (warp >= N) return;
    int i = warp;
    float4 q = ((const float4*)Q)[(size_t)i * 32 + lane];
    bool isbyte = (g_validbyte != 0);
    float d[KNBR];
    #pragma unroll
    for (int j = 0; j < KNBR; j++) {
        int nb = nbr[(size_t)i * KNBR + j];
        int vld = isbyte ? (int)((const unsigned char*)validp)[(size_t)i * KNBR + j]
                         : ((const int*)validp)[(size_t)i * KNBR + j];
        bool masked = (vld == 0) || (rs[nb] == 0.0f);
        float4 k4 = ((const float4*)Kp)[(size_t)nb * 32 + lane];
        float p = q.x * k4.x + q.y * k4.y + q.z * k4.z + q.w * k4.w;
        p += __shfl_xor_sync(0xffffffffu, p, 1);
        p += __shfl_xor_sync(0xffffffffu, p, 2);
        d[j] = masked ? -1e30f : p * 0.25f;   // dh^-0.5 = 1/4
    }
    float m = d[0];
    #pragma unroll
    for (int j = 1; j < KNBR; j++) m = fmaxf(m, d[j]);
    float e[KNBR], s = 0.f;
    #pragma unroll
    for (int j = 0; j < KNBR; j++) { e[j] = __expf(d[j] - m); s += e[j]; }
    float inv = 1.f / s;
    if ((lane & 3) == 0) {
        int h = lane >> 2;
        #pragma unroll
        for (int j = 0; j < KNBR; j++)
            aw[(size_t)i * 40 + j * 8 + h] = e[j] * inv;
    }
}

// pass 2: gather V only; out = sum_j a[j] * V[nb_j]  (tf32-rounded)
__global__ void attn_apply(const float* __restrict__ Vp, const int* __restrict__ nbr,
                           const float* __restrict__ aw, float* __restrict__ out, int N) {
    int warp = (blockIdx.x * blockDim.x + threadIdx.x) >> 5;
    int lane = threadIdx.x & 31;
    if (warp >= N) return;
    int i = warp;
    int h = lane >> 2;
    float a[KNBR];
    #pragma unroll
    for (int j = 0; j < KNBR; j++)
        a[j] = aw[(size_t)i * 40 + j * 8 + h];
    float4 o = make_float4(0.f, 0.f, 0.f, 0.f);
    #pragma unroll
    for (int j = 0; j < KNBR; j++) {
        int nb = nbr[(size_t)i * KNBR + j];
        float4 v = ((const float4*)Vp)[(size_t)nb * 32 + lane];
        o.x += a[j] * v.x; o.y += a[j] * v.y; o.z += a[j] * v.z; o.w += a[j] * v.w;
    }
    o.x = rnd_tf32(o.x); o.y = rnd_tf32(o.y);
    o.z = rnd_tf32(o.z); o.w = rnd_tf32(o.w);
    ((float4*)out)[(size_t)i * 32 + lane] = o;
}

// ---------------- host orchestration ----------------------------------------
extern "C" void kernel_launch(void* const* d_in, const int* in_sizes, int n_in,
                              void* d_out, int out_size) {
    const float* feat  = (const float*)d_in[0];
    const int*   nbr   = (const int*)d_in[1];
    const void*  valid = d_in[2];
    const float* wq1 = (const float*)d_in[3];
    const float* wk1 = (const float*)d_in[4];
    const float* wv1 = (const float*)d_in[5];
    const float* wo1 = (const float*)d_in[6];
    const float* bo1 = (const float*)d_in[7];
    const float* w1a = (const float*)d_in[8];
    const float* b1a = (const float*)d_in[9];
    const float* w1b = (const float*)d_in[10];
    const float* b1b = (const float*)d_in[11];
    const float* g1a = (const float*)d_in[12];
    const float* be1a= (const float*)d_in[13];
    const float* g1b = (const float*)d_in[14];
    const float* be1b= (const float*)d_in[15];
    const float* wq2 = (const float*)d_in[16];
    const float* wk2 = (const float*)d_in[17];
    const float* wv2 = (const float*)d_in[18];
    const float* wo2 = (const float*)d_in[19];
    const float* bo2 = (const float*)d_in[20];
    const float* w2a = (const float*)d_in[21];
    const float* b2a = (const float*)d_in[22];
    const float* w2b = (const float*)d_in[23];
    const float* b2b = (const float*)d_in[24];
    const float* g2a = (const float*)d_in[25];
    const float* be2a= (const float*)d_in[26];
    const float* g2b = (const float*)d_in[27];
    const float* be2b= (const float*)d_in[28];
    const float* w4  = (const float*)d_in[29];
    const float* b4  = (const float*)d_in[30];

    int N = in_sizes[0] / D;

    float *Q1, *K1, *V1, *K2, *V2, *Q2, *ATT, *XB, *RS, *WR, *AW;
    cudaGetSymbolAddress((void**)&Q1,  g_Q1);
    cudaGetSymbolAddress((void**)&K1,  g_K1);
    cudaGetSymbolAddress((void**)&V1,  g_V1);
    cudaGetSymbolAddress((void**)&K2,  g_K2);
    cudaGetSymbolAddress((void**)&V2,  g_V2);
    cudaGetSymbolAddress((void**)&Q2,  g_Q2);
    cudaGetSymbolAddress((void**)&ATT, g_ATT);
    cudaGetSymbolAddress((void**)&XB,  g_XB);
    cudaGetSymbolAddress((void**)&RS,  g_rs);
    cudaGetSymbolAddress((void**)&WR,  g_Wr);
    cudaGetSymbolAddress((void**)&AW,  g_aw);

    int MB64 = (N + 63) / 64;
    int WPB  = (N + 7) / 8;

    const int PROJ_SMEM  = (8 * 64 * 20 + 2 * 16 * 136) * 4;                   // 58368 B
    const int LAYER_SMEM = (2 * 8 * 64 * 20 + 2 * 16 * 136 + 64 * 4 * 2) * 4;  // 101376 B
    cudaFuncSetAttribute(proj5_kernel, cudaFuncAttributeMaxDynamicSharedMemorySize, PROJ_SMEM);
    cudaFuncSetAttribute(layer_kernel<128, 1, 0>, cudaFuncAttributeMaxDynamicSharedMemorySize, LAYER_SMEM);
    cudaFuncSetAttribute(layer_kernel<64, 0, 1>,  cudaFuncAttributeMaxDynamicSharedMemorySize, LAYER_SMEM);

    detect_valid_kernel<<<1, 1024>>>((const unsigned char*)valid, N * KNBR);

    // pre-round all mma weight operands to tf32
    PrepList pl;
    const float* srcs[13] = {wq1, wk1, wv1, wk2, wv2, wo1, w1a, w1b, wq2, wo2, w2a, w2b, w4};
    int lens[13] = {16384,16384,16384,16384,16384, 16384, 32768, 32768, 16384, 16384, 32768, 32768, 8192};
    int offs[13] = {OFF_WQ1,OFF_WK1,OFF_WV1,OFF_WK2,OFF_WV2, OFF_WO1, OFF_W1A, OFF_W1B,
                    OFF_WQ2, OFF_WO2, OFF_W2A, OFF_W2B, OFF_W4};
    for (int e = 0; e < 13; e++) { pl.src[e] = srcs[e]; pl.len[e] = lens[e]; pl.off[e] = offs[e]; }
    prep_weights<<<120, 256>>>(pl, WR);

    Proj5 p;
    p.W[0] = WR + OFF_WQ1; p.W[1] = WR + OFF_WK1; p.W[2] = WR + OFF_WV1;
    p.W[3] = WR + OFF_WK2; p.W[4] = WR + OFF_WV2;
    p.Y[0] = Q1;  p.Y[1] = K1;  p.Y[2] = V1;  p.Y[3] = K2;  p.Y[4] = V2;
    proj5_kernel<<<MB64, 256, PROJ_SMEM>>>(feat, p, RS, N);

    // ---- layer 1: two-pass attn, then mega layer (writes XB and Q2) ----
    attn_dots<<<WPB, 256>>>(Q1, K1, nbr, valid, RS, AW, N);
    attn_apply<<<WPB, 256>>>(V1, nbr, AW, ATT, N);
    layer_kernel<128, 1, 0><<<MB64, 256, LAYER_SMEM>>>(
        ATT, WR + OFF_WO1, bo1, feat, g1a, be1a, WR + OFF_W1A, b1a, WR + OFF_W1B, b1b, g1b, be1b,
        WR + OFF_WQ2, nullptr, XB, Q2, N);

    // ---- layer 2: post = tanh(XB@w4 + b4) straight to d_out ----
    attn_dots<<<WPB, 256>>>(Q2, K2, nbr, valid, RS, AW, N);
    attn_apply<<<WPB, 256>>>(V2, nbr, AW, ATT, N);
    layer_kernel<64, 0, 1><<<MB64, 256, LAYER_SMEM>>>(
        ATT, WR + OFF_WO2, bo2, XB, g2a, be2a, WR + OFF_W2A, b2a, WR + OFF_W2B, b2b, g2b, be2b,
        WR + OFF_W4, b4, nullptr, (float*)d_out, N);
}

// round 17
// speedup vs baseline: 1.1342x; 1.1342x over previous
#include <cuda_runtime.h>
#include <cuda_fp16.h>
#include <math.h>

#define D 128
#define KNBR 5
#define NMAX 300000

// ---------------- scratch (static device memory; no allocations allowed) ----
__device__ float  g_Q1[(size_t)NMAX * D];
__device__ float  g_Q2[(size_t)NMAX * D];
__device__ __half g_KV1[(size_t)NMAX * 256];   // [node][K 128h | V 128h]
__device__ __half g_KV2[(size_t)NMAX * 256];
__device__ float  g_ATT[(size_t)NMAX * D];
__device__ float  g_XB[(size_t)NMAX * D];
__device__ float  g_rs[NMAX];
__device__ int    g_validbyte;
__device__ float  g_Wr[270336];                // tf32-pre-rounded weights

#define OFF_WQ1 0
#define OFF_WK1 16384
#define OFF_WV1 32768
#define OFF_WK2 49152
#define OFF_WV2 65536
#define OFF_WO1 81920
#define OFF_W1A 98304
#define OFF_W1B 131072
#define OFF_WQ2 163840
#define OFF_WO2 180224
#define OFF_W2A 196608
#define OFF_W2B 229376
#define OFF_W4  262144

// ---------------- detect whether nbr_valid is byte-bool or int32 ------------
__global__ void detect_valid_kernel(const unsigned char* __restrict__ p, int nelem) {
    if (threadIdx.x == 0) g_validbyte = 0;
    __syncthreads();
    int lim = nelem < 4096 ? nelem : 4096;
    int found = 0;
    for (int j = threadIdx.x; j < lim; j += blockDim.x)
        if ((j & 3) && p[j]) found = 1;
    if (found) g_validbyte = 1;
}

// ---------------- tf32 / mma / cp.async helpers ------------------------------
__device__ __forceinline__ unsigned f2tf32(float f) {
    unsigned u;
    asm("cvt.rna.tf32.f32 %0, %1;" : "=r"(u) : "f"(f));
    return u;
}
__device__ __forceinline__ float rnd_tf32(float f) { return __uint_as_float(f2tf32(f)); }

__device__ __forceinline__ void mma_tf32(float* c, const unsigned* a, const unsigned* b) {
    asm volatile(
        "mma.sync.aligned.m16n8k8.row.col.f32.tf32.tf32.f32 "
        "{%0,%1,%2,%3}, {%4,%5,%6,%7}, {%8,%9}, {%0,%1,%2,%3};"
        : "+f"(c[0]), "+f"(c[1]), "+f"(c[2]), "+f"(c[3])
        : "r"(a[0]), "r"(a[1]), "r"(a[2]), "r"(a[3]), "r"(b[0]), "r"(b[1]));
}

__device__ __forceinline__ void cp16(float* dst, const float* src, bool pred) {
    unsigned sa = (unsigned)__cvta_generic_to_shared(dst);
    int sz = pred ? 16 : 0;
    asm volatile("cp.async.cg.shared.global [%0], [%1], 16, %2;"
                 :: "r"(sa), "l"(src), "r"(sz) : "memory");
}
#define CP_COMMIT asm volatile("cp.async.commit_group;" ::: "memory")
__device__ __forceinline__ void cp_wait0() { asm volatile("cp.async.wait_group 0;" ::: "memory"); }

// ---------------- weight pre-rounding pass -----------------------------------
struct PrepList { const float* src[13]; int len[13]; int off[13]; };

__global__ void prep_weights(PrepList pl, float* __restrict__ dst) {
    int stride = gridDim.x * blockDim.x;
    int t = blockIdx.x * blockDim.x + threadIdx.x;
    #pragma unroll 1
    for (int e = 0; e < 13; e++) {
        const float* s = pl.src[e];
        float* d = dst + pl.off[e];
        for (int i = t; i < pl.len[e]; i += stride)
            d[i] = rnd_tf32(s[i]);
    }
}

// ============================================================================
//  Fragment compute: A chunk [64][20], B stage [16][136]; pre-rounded operands.
// ============================================================================
template <int NT>
__device__ __forceinline__ void compute_stageN(
    const float* __restrict__ Asm, const float* __restrict__ Bsm,
    int lane, int mrow, int ncol, float (&c)[2][NT][4])
{
    #pragma unroll
    for (int ks = 0; ks < 16; ks += 8) {
        int kq = ks + (lane & 3);
        unsigned a[2][4], b[NT][2];
        #pragma unroll
        for (int mt = 0; mt < 2; mt++) {
            int row = mrow + mt * 16 + (lane >> 2);
            a[mt][0] = __float_as_uint(Asm[row * 20 + kq]);
            a[mt][1] = __float_as_uint(Asm[(row + 8) * 20 + kq]);
            a[mt][2] = __float_as_uint(Asm[row * 20 + kq + 4]);
            a[mt][3] = __float_as_uint(Asm[(row + 8) * 20 + kq + 4]);
        }
        #pragma unroll
        for (int nt = 0; nt < NT; nt++) {
            int col = ncol + nt * 8 + (lane >> 2);
            b[nt][0] = __float_as_uint(Bsm[kq * 136 + col]);
            b[nt][1] = __float_as_uint(Bsm[(kq + 4) * 136 + col]);
        }
        #pragma unroll
        for (int mt = 0; mt < 2; mt++)
            #pragma unroll
            for (int nt = 0; nt < NT; nt++)
                mma_tf32(c[mt][nt], a[mt], b[nt]);
    }
}

// Stream B (K=128, 8 stages of 16) against a resident A region [8][64][20].
// ONE __syncthreads per stage: wait0 -> sync -> issue(it+1) -> compute(it).
template <int NT>
__device__ __forceinline__ void gemm_stream(
    const float* __restrict__ Areg, const float* __restrict__ W,
    int pitch, int colOff, float* __restrict__ Bsm,
    int tid, int lane, int mrow, int ncol, float (&c)[2][NT][4])
{
    constexpr int PERROW = NT * 8;            // cp16 per B k-row
    constexpr int ITER   = (16 * PERROW) / 256;
    #pragma unroll
    for (int r = 0; r < ITER; r++) {
        int idx = tid + r * 256;
        int bk = idx / PERROW, bc = (idx % PERROW) * 4;
        cp16(&Bsm[bk * 136 + bc], W + (size_t)bk * pitch + colOff + bc, true);
    }
    CP_COMMIT;
    #pragma unroll
    for (int it = 0; it < 8; it++) {
        cp_wait0();
        __syncthreads();
        if (it < 7) {
            int st = (it + 1) & 1, k0 = (it + 1) * 16;
            #pragma unroll
            for (int r = 0; r < ITER; r++) {
                int idx = tid + r * 256;
                int bk = idx / PERROW, bc = (idx % PERROW) * 4;
                cp16(&Bsm[st * 2176 + bk * 136 + bc],
                     W + (size_t)(k0 + bk) * pitch + colOff + bc, true);
            }
            CP_COMMIT;
        }
        compute_stageN<NT>(Areg + it * 1280, Bsm + (it & 1) * 2176, lane, mrow, ncol, c);
    }
}

// bias + residual (global or smem A-layout) + LayerNorm; output (tf32-rounded)
// to smem A-layout and/or global. Overwrites c with pre-LN values.
__device__ __forceinline__ void ln_epi(
    float (&c)[2][4][4], const float* __restrict__ bias,
    const float* __restrict__ resg, const float* __restrict__ ressm,
    const float* __restrict__ gam, const float* __restrict__ bet,
    float2* __restrict__ red, float* __restrict__ outsm, float* __restrict__ outg,
    int row0, int M, int lane, int warp, int mrow, int ncol)
{
    int warpN = warp & 3;
    #pragma unroll
    for (int mt = 0; mt < 2; mt++)
        #pragma unroll
        for (int rh = 0; rh < 2; rh++) {
            int rl = mrow + mt * 16 + rh * 8 + (lane >> 2);
            bool ok = row0 + rl < M;
            float s = 0.f, sq = 0.f;
            #pragma unroll
            for (int nt = 0; nt < 4; nt++) {
                int col = ncol + nt * 8 + (lane & 3) * 2;
                float2 rr;
                if (ressm) rr = *(const float2*)&ressm[(col >> 4) * 1280 + rl * 20 + (col & 15)];
                else rr = ok ? *(const float2*)&resg[(size_t)(row0 + rl) * 128 + col]
                             : make_float2(0.f, 0.f);
                float2 bb = *(const float2*)&bias[col];
                float x0 = c[mt][nt][rh * 2 + 0] + rr.x + bb.x;
                float x1 = c[mt][nt][rh * 2 + 1] + rr.y + bb.y;
                c[mt][nt][rh * 2 + 0] = x0;
                c[mt][nt][rh * 2 + 1] = x1;
                s += x0 + x1;
                sq += x0 * x0 + x1 * x1;
            }
            s  += __shfl_xor_sync(0xffffffffu, s, 1);
            s  += __shfl_xor_sync(0xffffffffu, s, 2);
            sq += __shfl_xor_sync(0xffffffffu, sq, 1);
            sq += __shfl_xor_sync(0xffffffffu, sq, 2);
            if ((lane & 3) == 0) red[rl * 4 + warpN] = make_float2(s, sq);
        }
    __syncthreads();
    #pragma unroll
    for (int mt = 0; mt < 2; mt++)
        #pragma unroll
        for (int rh = 0; rh < 2; rh++) {
            int rl = mrow + mt * 16 + rh * 8 + (lane >> 2);
            float s = 0.f, sq = 0.f;
            #pragma unroll
            for (int wN = 0; wN < 4; wN++) { float2 e = red[rl * 4 + wN]; s += e.x; sq += e.y; }
            float mean = s * (1.f / 128.f);
            float var  = sq * (1.f / 128.f) - mean * mean;
            float rstd = rsqrtf(var + 1e-5f);
            bool ok = row0 + rl < M;
            #pragma unroll
            for (int nt = 0; nt < 4; nt++) {
                int col = ncol + nt * 8 + (lane & 3) * 2;
                float2 gg = *(const float2*)&gam[col];
                float2 ee = *(const float2*)&bet[col];
                float2 o;
                o.x = rnd_tf32((c[mt][nt][rh * 2 + 0] - mean) * rstd * gg.x + ee.x);
                o.y = rnd_tf32((c[mt][nt][rh * 2 + 1] - mean) * rstd * gg.y + ee.y);
                if (outsm) *(float2*)&outsm[(col >> 4) * 1280 + rl * 20 + (col & 15)] = o;
                if (outg && ok) *(float2*)&outg[(size_t)(row0 + rl) * 128 + col] = o;
            }
        }
    __syncthreads();
}

// relu(c + bias) -> smem A-layout (tf32-rounded); zeros c for reuse.
__device__ __forceinline__ void store_relu_sm(
    float (&c)[2][4][4], const float* __restrict__ bias, float* __restrict__ outsm,
    int lane, int mrow, int ncol)
{
    #pragma unroll
    for (int mt = 0; mt < 2; mt++)
        #pragma unroll
        for (int rh = 0; rh < 2; rh++) {
            int rl = mrow + mt * 16 + rh * 8 + (lane >> 2);
            #pragma unroll
            for (int nt = 0; nt < 4; nt++) {
                int col = ncol + nt * 8 + (lane & 3) * 2;
                float2 bb = *(const float2*)&bias[col];
                float2 o;
                o.x = rnd_tf32(fmaxf(c[mt][nt][rh * 2 + 0] + bb.x, 0.f));
                o.y = rnd_tf32(fmaxf(c[mt][nt][rh * 2 + 1] + bb.y, 0.f));
                *(float2*)&outsm[(col >> 4) * 1280 + rl * 20 + (col & 15)] = o;
                c[mt][nt][rh * 2 + 0] = 0.f;
                c[mt][nt][rh * 2 + 1] = 0.f;
            }
        }
}

// ============================================================================
//  Mega layer kernel: 64-row tile, 256 threads, 2 CTAs/SM.
// ============================================================================
template <int NP, int WRITE_XB, int POSTTANH>
__global__ void __launch_bounds__(256, 2) layer_kernel(
    const float* __restrict__ ATT, const float* __restrict__ wo, const float* __restrict__ bo,
    const float* __restrict__ res, const float* __restrict__ ga, const float* __restrict__ bea,
    const float* __restrict__ wa, const float* __restrict__ ba,
    const float* __restrict__ wb, const float* __restrict__ bb,
    const float* __restrict__ gb, const float* __restrict__ beb,
    const float* __restrict__ Wp, const float* __restrict__ bp,
    float* __restrict__ XB, float* __restrict__ Yp, int M)
{
    extern __shared__ float sm[];
    float*  R1  = sm;                        // XA, [8][64][20]
    float*  R2  = R1 + 8 * 64 * 20;          // ATT / H-half / XB tile
    float*  Bsm = R2 + 8 * 64 * 20;          // [2][16][136]
    float2* red = (float2*)(Bsm + 2 * 16 * 136);   // [64][4]

    int row0 = blockIdx.x * 64;
    int tid = threadIdx.x, lane = tid & 31, warp = tid >> 5;
    int mrow = (warp >> 2) * 32;
    int ncol = (warp & 3) * 32;

    // stage ATT tile -> R2 (ATT is pre-rounded tf32 by attn_kernel)
    {
        int row = tid >> 2, seg = (tid & 3) * 4;
        bool ok = row0 + row < M;
        const float* src = ATT + (size_t)(row0 + row) * 128 + seg;
        #pragma unroll
        for (int kc = 0; kc < 8; kc++)
            cp16(&R2[kc * 1280 + row * 20 + seg], ok ? src + kc * 16 : ATT, ok);
        CP_COMMIT;
    }

    float cA[2][4][4] = {};
    float cB[2][4][4] = {};

    // P1: cA = ATT @ wo
    gemm_stream<4>(R2, wo, 128, 0, Bsm, tid, lane, mrow, ncol, cA);
    // P2: XA = LN(cA + bo + res) -> R1 (smem only)
    ln_epi(cA, bo, res, nullptr, ga, bea, red, R1, nullptr, row0, M, lane, warp, mrow, ncol);

    #pragma unroll
    for (int mt = 0; mt < 2; mt++)
        #pragma unroll
        for (int nt = 0; nt < 4; nt++)
            #pragma unroll
            for (int q = 0; q < 4; q++) cA[mt][nt][q] = 0.f;

    // FFN in two 128-col halves, H resident in R2
    #pragma unroll
    for (int h = 0; h < 2; h++) {
        gemm_stream<4>(R1, wa, 256, h * 128, Bsm, tid, lane, mrow, ncol, cA);
        store_relu_sm(cA, ba + h * 128, R2, lane, mrow, ncol);   // also zeros cA
        gemm_stream<4>(R2, wb + (size_t)h * 128 * 128, 128, 0, Bsm, tid, lane, mrow, ncol, cB);
    }

    // XB = LN(cB + bb + XA[smem]) -> R2 (for post) and optionally global
    ln_epi(cB, bb, nullptr, R1, gb, beb, red, R2, WRITE_XB ? XB : nullptr,
           row0, M, lane, warp, mrow, ncol);

    // post: Yp = act(XB @ Wp + bp)
    constexpr int NTP = NP / 32;
    int ncolp = (warp & 3) * (NTP * 8);
    float cP[2][NTP][4] = {};
    gemm_stream<NTP>(R2, Wp, NP, 0, Bsm, tid, lane, mrow, ncolp, cP);

    const bool hasb = (bp != nullptr);
    #pragma unroll
    for (int mt = 0; mt < 2; mt++)
        #pragma unroll
        for (int rh = 0; rh < 2; rh++) {
            int rl = mrow + mt * 16 + rh * 8 + (lane >> 2);
            if (row0 + rl >= M) continue;
            #pragma unroll
            for (int nt = 0; nt < NTP; nt++) {
                int col = ncolp + nt * 8 + (lane & 3) * 2;
                float bx = 0.f, by = 0.f;
                if (hasb) { float2 v = *(const float2*)&bp[col]; bx = v.x; by = v.y; }
                float x0 = cP[mt][nt][rh * 2 + 0] + bx;
                float x1 = cP[mt][nt][rh * 2 + 1] + by;
                if (POSTTANH) { x0 = tanhf(x0); x1 = tanhf(x1); }
                *(float2*)&Yp[(size_t)(row0 + rl) * NP + col] = make_float2(x0, x1);
            }
        }
}

// ---------------- proj5: fused 5-way projection, 64-row tile, 2 CTAs/SM ------
// Projection 0 -> Q1 (fp32); 1,2 -> KV1 (K,V fp16); 3,4 -> KV2 (K,V fp16).
struct Proj5 { const float* W[5]; };

__global__ void __launch_bounds__(256, 2) proj5_kernel(
    const float* __restrict__ X, Proj5 p, float* __restrict__ Q1,
    __half* __restrict__ KV1, __half* __restrict__ KV2,
    float* __restrict__ rs, int M)
{
    extern __shared__ float sm[];
    float* Af = sm;                          // [8][64][20]
    float* Bs = sm + 8 * 64 * 20;            // [2][16][136]
    int row0 = blockIdx.x * 64;
    int tid = threadIdx.x, lane = tid & 31, warp = tid >> 5;
    int mrow = (warp >> 2) * 32, ncol = (warp & 3) * 32;

    // load full A tile (8 k-chunks), 4 threads per row
    {
        int row = tid >> 2, seg = (tid & 3) * 4;
        bool ok = (row0 + row) < M;
        const float* sa = X + (size_t)(row0 + row) * 128 + seg;
        #pragma unroll
        for (int kc = 0; kc < 8; kc++)
            cp16(&Af[kc * 1280 + row * 20 + seg], ok ? sa + kc * 16 : X, ok);
        CP_COMMIT;
    }
    int s_bk = tid >> 4;
    int s_bc = (tid & 15) * 8;
    {
        const float* sb = p.W[0] + (size_t)s_bk * 128 + s_bc;
        cp16(&Bs[s_bk * 136 + s_bc],     sb,     true);
        cp16(&Bs[s_bk * 136 + s_bc + 4], sb + 4, true);
        CP_COMMIT;
    }

    float c[2][4][4] = {};
    for (int it = 0; it < 40; it++) {
        int kc = it & 7;
        cp_wait0();
        __syncthreads();
        if (it + 1 < 40) {
            int st = (it + 1) & 1;
            const float* Wn = p.W[(it + 1) >> 3];
            int k0 = ((it + 1) & 7) * 16;
            const float* sb = Wn + (size_t)(k0 + s_bk) * 128 + s_bc;
            cp16(&Bs[st * 2176 + s_bk * 136 + s_bc],     sb,     true);
            cp16(&Bs[st * 2176 + s_bk * 136 + s_bc + 4], sb + 4, true);
            CP_COMMIT;
        }
        if (it == 0) {
            // rowsum for the mask, from the resident A tile (4 threads/row)
            int row = tid >> 2, part = tid & 3;
            float s = 0.f;
            #pragma unroll
            for (int q = 0; q < 2; q++) {
                int kcc = part * 2 + q;
                #pragma unroll
                for (int kl = 0; kl < 16; kl++) s += Af[kcc * 1280 + row * 20 + kl];
            }
            s += __shfl_xor_sync(0xffffffffu, s, 1);
            s += __shfl_xor_sync(0xffffffffu, s, 2);
            if ((lane & 3) == 0 && row0 + row < M) rs[row0 + row] = s;
        }
        compute_stageN<4>(Af + kc * 1280, Bs + (it & 1) * 2176, lane, mrow, ncol, c);
        if (kc == 7) {
            int pp = it >> 3;
            __half* KVp = (pp <= 2) ? KV1 : KV2;
            int koff = (pp == 1 || pp == 3) ? 0 : 128;
            #pragma unroll
            for (int mt = 0; mt < 2; mt++)
                #pragma unroll
                for (int nt = 0; nt < 4; nt++) {
                    int col = ncol + nt * 8 + (lane & 3) * 2;
                    #pragma unroll
                    for (int rh = 0; rh < 2; rh++) {
                        int row = row0 + mrow + mt * 16 + rh * 8 + (lane >> 2);
                        float c0 = c[mt][nt][rh * 2 + 0];
                        float c1 = c[mt][nt][rh * 2 + 1];
                        if (row < M) {
                            if (pp == 0)
                                *(float2*)&Q1[(size_t)row * 128 + col] = make_float2(c0, c1);
                            else
                                *(__half2*)&KVp[(size_t)row * 256 + koff + col] =
                                    __floats2half2_rn(c0, c1);
                        }
                        c[mt][nt][rh * 2 + 0] = 0.f;
                        c[mt][nt][rh * 2 + 1] = 0.f;
                    }
                }
        }
    }
}

// ---------------- warp-per-node attention, fp16 interleaved K/V --------------
__global__ void attn_kernel(const float* __restrict__ Q, const __half* __restrict__ KV,
                            const int* __restrict__ nbr, const void* __restrict__ validp,
                            const float* __restrict__ rs, float* __restrict__ out, int N) {
    int warp = (blockIdx.x * blockDim.x + threadIdx.x) >> 5;
    int lane = threadIdx.x & 31;
    if (warp >= N) return;
    int i = warp;
    float4 q = ((const float4*)Q)[(size_t)i * 32 + lane];
    bool isbyte = (g_validbyte != 0);
    float d[KNBR];
    uint2 vr[KNBR];
    #pragma unroll
    for (int j = 0; j < KNBR; j++) {
        int nb = nbr[(size_t)i * KNBR + j];
        int vld = isbyte ? (int)((const unsigned char*)validp)[(size_t)i * KNBR + j]
                         : ((const int*)validp)[(size_t)i * KNBR + j];
        bool masked = (vld == 0) || (rs[nb] == 0.0f);
        const uint2* row = (const uint2*)(KV + (size_t)nb * 256);
        uint2 kr = row[lane];          // K halves [4l,4l+4)
        vr[j]    = row[32 + lane];     // V halves [4l,4l+4)
        float2 k01 = __half22float2(*(__half2*)&kr.x);
        float2 k23 = __half22float2(*(__half2*)&kr.y);
        float p = q.x * k01.x + q.y * k01.y + q.z * k23.x + q.w * k23.y;
        p += __shfl_xor_sync(0xffffffffu, p, 1);
        p += __shfl_xor_sync(0xffffffffu, p, 2);
        d[j] = masked ? -1e30f : p * 0.25f;   // dh^-0.5 = 1/4
    }
    float m = d[0];
    #pragma unroll
    for (int j = 1; j < KNBR; j++) m = fmaxf(m, d[j]);
    float e[KNBR], s = 0.f;
    #pragma unroll
    for (int j = 0; j < KNBR; j++) { e[j] = __expf(d[j] - m); s += e[j]; }
    float inv = 1.f / s;
    float4 o = make_float4(0.f, 0.f, 0.f, 0.f);
    #pragma unroll
    for (int j = 0; j < KNBR; j++) {
        float a = e[j] * inv;
        float2 v01 = __half22float2(*(__half2*)&vr[j].x);
        float2 v23 = __half22float2(*(__half2*)&vr[j].y);
        o.x += a * v01.x; o.y += a * v01.y; o.z += a * v23.x; o.w += a * v23.y;
    }
    o.x = rnd_tf32(o.x); o.y = rnd_tf32(o.y);
    o.z = rnd_tf32(o.z); o.w = rnd_tf32(o.w);
    ((float4*)out)[(size_t)i * 32 + lane] = o;
}

// ---------------- host orchestration ----------------------------------------
extern "C" void kernel_launch(void* const* d_in, const int* in_sizes, int n_in,
                              void* d_out, int out_size) {
    const float* feat  = (const float*)d_in[0];
    const int*   nbr   = (const int*)d_in[1];
    const void*  valid = d_in[2];
    const float* wq1 = (const float*)d_in[3];
    const float* wk1 = (const float*)d_in[4];
    const float* wv1 = (const float*)d_in[5];
    const float* wo1 = (const float*)d_in[6];
    const float* bo1 = (const float*)d_in[7];
    const float* w1a = (const float*)d_in[8];
    const float* b1a = (const float*)d_in[9];
    const float* w1b = (const float*)d_in[10];
    const float* b1b = (const float*)d_in[11];
    const float* g1a = (const float*)d_in[12];
    const float* be1a= (const float*)d_in[13];
    const float* g1b = (const float*)d_in[14];
    const float* be1b= (const float*)d_in[15];
    const float* wq2 = (const float*)d_in[16];
    const float* wk2 = (const float*)d_in[17];
    const float* wv2 = (const float*)d_in[18];
    const float* wo2 = (const float*)d_in[19];
    const float* bo2 = (const float*)d_in[20];
    const float* w2a = (const float*)d_in[21];
    const float* b2a = (const float*)d_in[22];
    const float* w2b = (const float*)d_in[23];
    const float* b2b = (const float*)d_in[24];
    const float* g2a = (const float*)d_in[25];
    const float* be2a= (const float*)d_in[26];
    const float* g2b = (const float*)d_in[27];
    const float* be2b= (const float*)d_in[28];
    const float* w4  = (const float*)d_in[29];
    const float* b4  = (const float*)d_in[30];

    int N = in_sizes[0] / D;

    float *Q1, *Q2, *ATT, *XB, *RS, *WR;
    __half *KV1, *KV2;
    cudaGetSymbolAddress((void**)&Q1,  g_Q1);
    cudaGetSymbolAddress((void**)&Q2,  g_Q2);
    cudaGetSymbolAddress((void**)&KV1, g_KV1);
    cudaGetSymbolAddress((void**)&KV2, g_KV2);
    cudaGetSymbolAddress((void**)&ATT, g_ATT);
    cudaGetSymbolAddress((void**)&XB,  g_XB);
    cudaGetSymbolAddress((void**)&RS,  g_rs);
    cudaGetSymbolAddress((void**)&WR,  g_Wr);

    int MB64 = (N + 63) / 64;
    int WPB  = (N + 7) / 8;

    const int PROJ_SMEM  = (8 * 64 * 20 + 2 * 16 * 136) * 4;                   // 58368 B
    const int LAYER_SMEM = (2 * 8 * 64 * 20 + 2 * 16 * 136 + 64 * 4 * 2) * 4;  // 101376 B
    cudaFuncSetAttribute(proj5_kernel, cudaFuncAttributeMaxDynamicSharedMemorySize, PROJ_SMEM);
    cudaFuncSetAttribute(layer_kernel<128, 1, 0>, cudaFuncAttributeMaxDynamicSharedMemorySize, LAYER_SMEM);
    cudaFuncSetAttribute(layer_kernel<64, 0, 1>,  cudaFuncAttributeMaxDynamicSharedMemorySize, LAYER_SMEM);

    detect_valid_kernel<<<1, 1024>>>((const unsigned char*)valid, N * KNBR);

    // pre-round all mma weight operands to tf32
    PrepList pl;
    const float* srcs[13] = {wq1, wk1, wv1, wk2, wv2, wo1, w1a, w1b, wq2, wo2, w2a, w2b, w4};
    int lens[13] = {16384,16384,16384,16384,16384, 16384, 32768, 32768, 16384, 16384, 32768, 32768, 8192};
    int offs[13] = {OFF_WQ1,OFF_WK1,OFF_WV1,OFF_WK2,OFF_WV2, OFF_WO1, OFF_W1A, OFF_W1B,
                    OFF_WQ2, OFF_WO2, OFF_W2A, OFF_W2B, OFF_W4};
    for (int e = 0; e < 13; e++) { pl.src[e] = srcs[e]; pl.len[e] = lens[e]; pl.off[e] = offs[e]; }
    prep_weights<<<120, 256>>>(pl, WR);

    Proj5 p;
    p.W[0] = WR + OFF_WQ1; p.W[1] = WR + OFF_WK1; p.W[2] = WR + OFF_WV1;
    p.W[3] = WR + OFF_WK2; p.W[4] = WR + OFF_WV2;
    proj5_kernel<<<MB64, 256, PROJ_SMEM>>>(feat, p, Q1, KV1, KV2, RS, N);

    // ---- layer 1: attn (fp16 KV gather), then mega layer (writes XB, Q2) ----
    attn_kernel<<<WPB, 256>>>(Q1, KV1, nbr, valid, RS, ATT, N);
    layer_kernel<128, 1, 0><<<MB64, 256, LAYER_SMEM>>>(
        ATT, WR + OFF_WO1, bo1, feat, g1a, be1a, WR + OFF_W1A, b1a, WR + OFF_W1B, b1b, g1b, be1b,
        WR + OFF_WQ2, nullptr, XB, Q2, N);

    // ---- layer 2: post = tanh(XB@w4 + b4) straight to d_out ----
    attn_kernel<<<WPB, 256>>>(Q2, KV2, nbr, valid, RS, ATT, N);
    layer_kernel<64, 0, 1><<<MB64, 256, LAYER_SMEM>>>(
        ATT, WR + OFF_WO2, bo2, XB, g2a, be2a, WR + OFF_W2A, b2a, WR + OFF_W2B, b2b, g2b, be2b,
        WR + OFF_W4, b4, nullptr, (float*)d_out, N);
}